// round 11
// baseline (speedup 1.0000x reference)
#include <cuda_runtime.h>
#include <cuda_fp16.h>
#include <cuda_bf16.h>
#include <mma.h>
#include <stdint.h>

using namespace nvcuda;

#define Bb 4
#define Ss 512
#define Mm 128
#define Hh 768
#define VSIZE 10000
#define KCH 64                   // k per smem chunk
#define NCH 6                    // chunks per CTA (K-split 2: 384 k each)
#define LDK 72                   // padded k-stride (elements) in smem tiles
#define PSTRIDE (Bb * Ss * Mm)

#define ATTN_BLOCKS 128                       // B * 16 stiles * 2 ksplit
#define CONV_N8     ((VSIZE * Hh) / 8)        // 960000 uint4 slots
#define CONV_BLOCKS ((CONV_N8 + 255) / 256)   // 3750

// scratch: fp16 value table (15 MB) + partial u (2 MB, [2][B][S][M])
__device__ __half g_vt[(long)VSIZE * Hh];
__device__ float  g_part[2 * PSTRIDE];

// ---------------------------------------------------------------------------
// Fused prep kernel.
//  blocks [0, 128):        wmma bf16 attention partials (L2/smem/tensor-bound,
//                          LOW issue occupancy -> leaves slots for conv)
//  blocks [128, 128+3750): value_table fp32->fp16 convert (DRAM-bound)
// R6's fused version failed because attn was ISSUE-bound fp32; wmma attn is not.
// ---------------------------------------------------------------------------
__global__ __launch_bounds__(256) void kvmn_fused_prep(
    const int*   __restrict__ word_seq,   // [B, M]
    const float* __restrict__ hidden,     // [B, S, H]
    const float* __restrict__ key_table,  // [KEY_SIZE, H]
    const float* __restrict__ vt)         // [VALUE_SIZE, H]
{
    const int t = threadIdx.x;

    if (blockIdx.x >= ATTN_BLOCKS) {
        // ---------------- conv path (no smem use, no barriers) ----------------
        long i = (long)(blockIdx.x - ATTN_BLOCKS) * 256 + t;   // one uint4 (8 fp16)
        if (i >= (long)CONV_N8) return;
        float4 a = ((const float4*)vt)[2 * i];
        float4 b = ((const float4*)vt)[2 * i + 1];
        __half2 p0 = __floats2half2_rn(a.x, a.y);
        __half2 p1 = __floats2half2_rn(a.z, a.w);
        __half2 p2 = __floats2half2_rn(b.x, b.y);
        __half2 p3 = __floats2half2_rn(b.z, b.w);
        uint4 r;
        r.x = *(uint32_t*)&p0;  r.y = *(uint32_t*)&p1;
        r.z = *(uint32_t*)&p2;  r.w = *(uint32_t*)&p3;
        ((uint4*)g_vt)[i] = r;
        return;
    }

    // ---------------- attn path (wmma bf16, K-split 2) ----------------
    __shared__ __nv_bfloat16 sA[32 * LDK];    // 32 s x 64 k (pad 72)
    __shared__ __nv_bfloat16 sB[Mm * LDK];    // 128 m x 64 k
    __shared__ int           sidx[Mm];

    const int warp = t >> 5;
    const int bid  = blockIdx.x;
    const int ksp  = bid & 1;
    const int stile = (bid >> 1) & 15;
    const int b    = bid >> 5;
    const int s0   = stile * 32;
    const int k_base = ksp * (Hh / 2);   // 0 or 384

    if (t < Mm) sidx[t] = word_seq[b * Mm + t];
    __syncthreads();

    wmma::fragment<wmma::accumulator, 16, 16, 16, float> acc[2];
#pragma unroll
    for (int j = 0; j < 2; j++) wmma::fill_fragment(acc[j], 0.0f);

    const int wr = (warp >> 2) * 16;   // warp s-row base: 0 or 16
    const int wc = (warp & 3) * 32;    // warp m-col base: 0,32,64,96

    const int arow = t >> 3, aseg = t & 7;   // A: 32 rows x 8-float segs
    const int brow = t >> 1, bhalf = t & 1;  // B: 128 rows x 32-float halves

    const float* hbase = hidden + ((long)(b * Ss + s0 + arow)) * Hh + k_base + aseg * 8;
    const float* kbase = key_table + (long)sidx[brow] * Hh + k_base + bhalf * 32;

    for (int c = 0; c < NCH; c++) {
        __syncthreads();
        // ---- A tile: 32 x 64
        {
            const float* hp = hbase + c * KCH;
            float4 u0 = *(const float4*)hp;
            float4 u1 = *(const float4*)(hp + 4);
            __nv_bfloat162 c0 = __floats2bfloat162_rn(u0.x, u0.y);
            __nv_bfloat162 c1 = __floats2bfloat162_rn(u0.z, u0.w);
            __nv_bfloat162 c2 = __floats2bfloat162_rn(u1.x, u1.y);
            __nv_bfloat162 c3 = __floats2bfloat162_rn(u1.z, u1.w);
            uint4 r;
            r.x = *(uint32_t*)&c0;  r.y = *(uint32_t*)&c1;
            r.z = *(uint32_t*)&c2;  r.w = *(uint32_t*)&c3;
            *(uint4*)(sA + arow * LDK + aseg * 8) = r;
        }
        // ---- B tile: 128 x 64
        {
            const float* kp = kbase + c * KCH;
            __nv_bfloat16* dst = sB + brow * LDK + bhalf * 32;
#pragma unroll
            for (int q = 0; q < 4; q++) {
                float4 v0 = *(const float4*)(kp + q * 8);
                float4 v1 = *(const float4*)(kp + q * 8 + 4);
                __nv_bfloat162 d0 = __floats2bfloat162_rn(v0.x, v0.y);
                __nv_bfloat162 d1 = __floats2bfloat162_rn(v0.z, v0.w);
                __nv_bfloat162 d2 = __floats2bfloat162_rn(v1.x, v1.y);
                __nv_bfloat162 d3 = __floats2bfloat162_rn(v1.z, v1.w);
                uint4 r;
                r.x = *(uint32_t*)&d0;  r.y = *(uint32_t*)&d1;
                r.z = *(uint32_t*)&d2;  r.w = *(uint32_t*)&d3;
                *(uint4*)(dst + q * 8) = r;
            }
        }
        __syncthreads();

#pragma unroll
        for (int ks = 0; ks < 4; ks++) {
            wmma::fragment<wmma::matrix_a, 16, 16, 16, __nv_bfloat16, wmma::row_major> fa;
            wmma::load_matrix_sync(fa, sA + wr * LDK + ks * 16, LDK);
#pragma unroll
            for (int j = 0; j < 2; j++) {
                wmma::fragment<wmma::matrix_b, 16, 16, 16, __nv_bfloat16, wmma::col_major> fb;
                wmma::load_matrix_sync(fb, sB + (wc + j * 16) * LDK + ks * 16, LDK);
                wmma::mma_sync(acc[j], fa, fb, acc[j]);
            }
        }
    }

    // epilogue: partials straight to the global plane
    float* dst = g_part + (long)ksp * PSTRIDE + ((long)(b * Ss + s0)) * Mm;
#pragma unroll
    for (int j = 0; j < 2; j++)
        wmma::store_matrix_sync(dst + wr * Mm + wc + j * 16, acc[j], Mm,
                                wmma::mem_row_major);
}

// ---------------------------------------------------------------------------
// Kernel B: fused softmax-combine (2 planes) + fp16 gather-accumulate.
// Grid: B*S = 2048 blocks, 192 threads. At the LTS roofline (~12.5 TB/s).
// ---------------------------------------------------------------------------
struct __align__(16) WP { const uint4* p; float w; float pad; };

__global__ __launch_bounds__(192) void kvmn_gather_kernel(
    const int*   __restrict__ labels,  // [B, S, M]
    const float* __restrict__ mask,    // [B, S, M]
    float*       __restrict__ out)     // [B, S, H]
{
    __shared__ WP    swp[Mm];
    __shared__ float osh[Hh];
    __shared__ float wsum[4];

    const int bs = blockIdx.x;
    const int t  = threadIdx.x;
    const float inv_temper = 1.0f / 27.712812921102035f;   // 1/sqrt(768)

    float ev = 0.0f;
    int   lab = 0;
    if (t < Mm) {
        long idx = (long)bs * Mm + t;
        float u  = (g_part[idx] + g_part[(long)PSTRIDE + idx]) * inv_temper;
        float mm = fminf(fmaxf(mask[idx], 0.0f), 1.0f);
        ev  = expf(u) * mm;
        lab = labels[idx];
    }
    float v = ev;
    v += __shfl_xor_sync(0xffffffffu, v, 16);
    v += __shfl_xor_sync(0xffffffffu, v, 8);
    v += __shfl_xor_sync(0xffffffffu, v, 4);
    v += __shfl_xor_sync(0xffffffffu, v, 2);
    v += __shfl_xor_sync(0xffffffffu, v, 1);
    if (t < Mm && (t & 31) == 0) wsum[t >> 5] = v;
    __syncthreads();
    float inv = 1.0f / (wsum[0] + wsum[1] + wsum[2] + wsum[3] + 1e-10f);
    if (t < Mm) {
        swp[t].p = (const uint4*)((const char*)g_vt + (long)lab * (Hh * 2));
        swp[t].w = ev * inv;
    }
    __syncthreads();

    const int half = t / 96;
    const int lane = t - half * 96;
    const int m0 = half * 64;

    float a[8];
#pragma unroll
    for (int q = 0; q < 8; q++) a[q] = 0.0f;

#pragma unroll 8
    for (int mi = 0; mi < 64; mi++) {
        WP e = swp[m0 + mi];
        uint4 r = e.p[lane];
        const float w = e.w;
        float2 f0 = __half22float2(*(__half2*)&r.x);
        float2 f1 = __half22float2(*(__half2*)&r.y);
        float2 f2 = __half22float2(*(__half2*)&r.z);
        float2 f3 = __half22float2(*(__half2*)&r.w);
        a[0] += w * f0.x;  a[1] += w * f0.y;
        a[2] += w * f1.x;  a[3] += w * f1.y;
        a[4] += w * f2.x;  a[5] += w * f2.y;
        a[6] += w * f3.x;  a[7] += w * f3.y;
    }

    if (half == 0) {
#pragma unroll
        for (int q = 0; q < 8; q++) osh[lane * 8 + q] = a[q];
    }
    __syncthreads();
    if (half == 1) {
        float* op = out + (long)bs * Hh + lane * 8;
#pragma unroll
        for (int q = 0; q < 8; q++) op[q] = a[q] + osh[lane * 8 + q];
    }
}

// ---------------------------------------------------------------------------
extern "C" void kernel_launch(void* const* d_in, const int* in_sizes, int n_in,
                              void* d_out, int out_size)
{
    const int*   word_seq   = (const int*)  d_in[0];  // [B, M]
    const float* hidden     = (const float*)d_in[1];  // [B, S, H]
    const int*   labels     = (const int*)  d_in[2];  // [B, S, M]
    const float* mask       = (const float*)d_in[3];  // [B, S, M]
    const float* key_table  = (const float*)d_in[4];  // [KEY_SIZE, H]
    const float* value_tab  = (const float*)d_in[5];  // [VALUE_SIZE, H]
    float*       out        = (float*)d_out;          // [B, S, H]

    kvmn_fused_prep<<<ATTN_BLOCKS + CONV_BLOCKS, 256>>>(word_seq, hidden,
                                                        key_table, value_tab);
    kvmn_gather_kernel<<<Bb * Ss, 192>>>(labels, mask, out);
}

// round 13
// speedup vs baseline: 1.6463x; 1.6463x over previous
#include <cuda_runtime.h>
#include <cuda_fp16.h>
#include <cuda_bf16.h>
#include <mma.h>
#include <stdint.h>

using namespace nvcuda;

#define Bb 4
#define Ss 512
#define Mm 128
#define Hh 768
#define VSIZE 10000
#define KCH 64                   // k per smem chunk
#define NCH 6                    // chunks per CTA (K-split 2: 384 k each)
#define LDK 72                   // padded k-stride (elements) in smem tiles
#define PSTRIDE (Bb * Ss * Mm)

// scratch: fp16 value table (15 MB) + partial u (2 MB, [2][B][S][M])
__device__ __half g_vt[(long)VSIZE * Hh];
__device__ float  g_part[2 * PSTRIDE];

// ---------------------------------------------------------------------------
// Kernel C: convert value_table fp32 -> fp16 (rn). 1 uint4/thread, 3750 blocks.
// __ldcs on the fp32 source: read-once stream, keep g_vt resident in L2.
// ---------------------------------------------------------------------------
__global__ __launch_bounds__(256) void kvmn_conv_kernel(const float* __restrict__ vt)
{
    long i = (long)blockIdx.x * 256 + threadIdx.x;          // one uint4 (8 fp16)
    const long n8 = (long)VSIZE * Hh / 8;
    if (i >= n8) return;
    float4 a = __ldcs((const float4*)vt + 2 * i);
    float4 b = __ldcs((const float4*)vt + 2 * i + 1);
    __half2 p0 = __floats2half2_rn(a.x, a.y);
    __half2 p1 = __floats2half2_rn(a.z, a.w);
    __half2 p2 = __floats2half2_rn(b.x, b.y);
    __half2 p3 = __floats2half2_rn(b.z, b.w);
    uint4 r;
    r.x = *(uint32_t*)&p0;  r.y = *(uint32_t*)&p1;
    r.z = *(uint32_t*)&p2;  r.w = *(uint32_t*)&p3;
    ((uint4*)g_vt)[i] = r;
}

// ---------------------------------------------------------------------------
// Kernel A (wmma bf16, K-split 2, double-buffered): partial u planes.
// Grid: B * 16 stiles * 2 ksplit = 128 CTAs, 256 threads (8 warps).
// CTA tile: 32s x 128m over its 384-k slice, 6 chunks of 64.
// Chunk c+1's LDG+cvt issue before chunk c's MMA; one sync per chunk.
// ---------------------------------------------------------------------------
__global__ __launch_bounds__(256) void kvmn_attn_wmma(
    const int*   __restrict__ word_seq,   // [B, M]
    const float* __restrict__ hidden,     // [B, S, H]
    const float* __restrict__ key_table)  // [KEY_SIZE, H]
{
    __shared__ __nv_bfloat16 sA[2][32 * LDK];    // 2 x 4.6 KB
    __shared__ __nv_bfloat16 sB[2][Mm * LDK];    // 2 x 18.4 KB
    __shared__ int           sidx[Mm];

    const int t    = threadIdx.x;
    const int warp = t >> 5;
    const int bid  = blockIdx.x;
    const int ksp  = bid & 1;
    const int stile = (bid >> 1) & 15;
    const int b    = bid >> 5;
    const int s0   = stile * 32;
    const int k_base = ksp * (Hh / 2);   // 0 or 384

    if (t < Mm) sidx[t] = word_seq[b * Mm + t];
    __syncthreads();

    wmma::fragment<wmma::accumulator, 16, 16, 16, float> acc[2];
#pragma unroll
    for (int j = 0; j < 2; j++) wmma::fill_fragment(acc[j], 0.0f);

    const int wr = (warp >> 2) * 16;   // warp s-row base: 0 or 16
    const int wc = (warp & 3) * 32;    // warp m-col base: 0,32,64,96

    const int arow = t >> 3, aseg = t & 7;   // A: 32 rows x 8-float segs
    const int brow = t >> 1, bhalf = t & 1;  // B: 128 rows x 32-float halves

    const float* hbase = hidden + ((long)(b * Ss + s0 + arow)) * Hh + k_base + aseg * 8;
    const float* kbase = key_table + (long)sidx[brow] * Hh + k_base + bhalf * 32;

    uint4 ra, rb[4];

    // load + convert chunk c into registers
    auto load_chunk = [&](int c, uint4& oa, uint4 ob[4]) {
        const float* hp = hbase + c * KCH;
        float4 u0 = *(const float4*)hp;
        float4 u1 = *(const float4*)(hp + 4);
        __nv_bfloat162 c0 = __floats2bfloat162_rn(u0.x, u0.y);
        __nv_bfloat162 c1 = __floats2bfloat162_rn(u0.z, u0.w);
        __nv_bfloat162 c2 = __floats2bfloat162_rn(u1.x, u1.y);
        __nv_bfloat162 c3 = __floats2bfloat162_rn(u1.z, u1.w);
        oa.x = *(uint32_t*)&c0;  oa.y = *(uint32_t*)&c1;
        oa.z = *(uint32_t*)&c2;  oa.w = *(uint32_t*)&c3;
        const float* kp = kbase + c * KCH;
#pragma unroll
        for (int q = 0; q < 4; q++) {
            float4 v0 = *(const float4*)(kp + q * 8);
            float4 v1 = *(const float4*)(kp + q * 8 + 4);
            __nv_bfloat162 d0 = __floats2bfloat162_rn(v0.x, v0.y);
            __nv_bfloat162 d1 = __floats2bfloat162_rn(v0.z, v0.w);
            __nv_bfloat162 d2 = __floats2bfloat162_rn(v1.x, v1.y);
            __nv_bfloat162 d3 = __floats2bfloat162_rn(v1.z, v1.w);
            ob[q].x = *(uint32_t*)&d0;  ob[q].y = *(uint32_t*)&d1;
            ob[q].z = *(uint32_t*)&d2;  ob[q].w = *(uint32_t*)&d3;
        }
    };
    auto store_chunk = [&](int buf, const uint4& ia, const uint4 ib[4]) {
        *(uint4*)(sA[buf] + arow * LDK + aseg * 8) = ia;
        __nv_bfloat16* dst = sB[buf] + brow * LDK + bhalf * 32;
#pragma unroll
        for (int q = 0; q < 4; q++) *(uint4*)(dst + q * 8) = ib[q];
    };

    load_chunk(0, ra, rb);
    store_chunk(0, ra, rb);
    __syncthreads();

#pragma unroll
    for (int c = 0; c < NCH; c++) {
        const int cur = c & 1;
        if (c + 1 < NCH) load_chunk(c + 1, ra, rb);   // overlap LDG with MMA

#pragma unroll
        for (int ks = 0; ks < 4; ks++) {
            wmma::fragment<wmma::matrix_a, 16, 16, 16, __nv_bfloat16, wmma::row_major> fa;
            wmma::load_matrix_sync(fa, sA[cur] + wr * LDK + ks * 16, LDK);
#pragma unroll
            for (int j = 0; j < 2; j++) {
                wmma::fragment<wmma::matrix_b, 16, 16, 16, __nv_bfloat16, wmma::col_major> fb;
                wmma::load_matrix_sync(fb, sB[cur] + (wc + j * 16) * LDK + ks * 16, LDK);
                wmma::mma_sync(acc[j], fa, fb, acc[j]);
            }
        }

        if (c + 1 < NCH) {
            store_chunk((c + 1) & 1, ra, rb);
            __syncthreads();
        }
    }

    // epilogue: partials straight to the global plane
    float* dst = g_part + (long)ksp * PSTRIDE + ((long)(b * Ss + s0)) * Mm;
#pragma unroll
    for (int j = 0; j < 2; j++)
        wmma::store_matrix_sync(dst + wr * Mm + wc + j * 16, acc[j], Mm,
                                wmma::mem_row_major);
}

// ---------------------------------------------------------------------------
// Kernel B: fused softmax-combine (2 planes) + fp16 gather-accumulate.
// Grid: B*S = 2048 blocks, 192 threads. At the LTS roofline (~12.5 TB/s).
// ---------------------------------------------------------------------------
struct __align__(16) WP { const uint4* p; float w; float pad; };

__global__ __launch_bounds__(192) void kvmn_gather_kernel(
    const int*   __restrict__ labels,  // [B, S, M]
    const float* __restrict__ mask,    // [B, S, M]
    float*       __restrict__ out)     // [B, S, H]
{
    __shared__ WP    swp[Mm];
    __shared__ float osh[Hh];
    __shared__ float wsum[4];

    const int bs = blockIdx.x;
    const int t  = threadIdx.x;
    const float inv_temper = 1.0f / 27.712812921102035f;   // 1/sqrt(768)

    float ev = 0.0f;
    int   lab = 0;
    if (t < Mm) {
        long idx = (long)bs * Mm + t;
        float u  = (g_part[idx] + g_part[(long)PSTRIDE + idx]) * inv_temper;
        float mm = fminf(fmaxf(mask[idx], 0.0f), 1.0f);
        ev  = expf(u) * mm;
        lab = labels[idx];
    }
    float v = ev;
    v += __shfl_xor_sync(0xffffffffu, v, 16);
    v += __shfl_xor_sync(0xffffffffu, v, 8);
    v += __shfl_xor_sync(0xffffffffu, v, 4);
    v += __shfl_xor_sync(0xffffffffu, v, 2);
    v += __shfl_xor_sync(0xffffffffu, v, 1);
    if (t < Mm && (t & 31) == 0) wsum[t >> 5] = v;
    __syncthreads();
    float inv = 1.0f / (wsum[0] + wsum[1] + wsum[2] + wsum[3] + 1e-10f);
    if (t < Mm) {
        swp[t].p = (const uint4*)((const char*)g_vt + (long)lab * (Hh * 2));
        swp[t].w = ev * inv;
    }
    __syncthreads();

    const int half = t / 96;
    const int lane = t - half * 96;
    const int m0 = half * 64;

    float a[8];
#pragma unroll
    for (int q = 0; q < 8; q++) a[q] = 0.0f;

#pragma unroll 8
    for (int mi = 0; mi < 64; mi++) {
        WP e = swp[m0 + mi];
        uint4 r = e.p[lane];
        const float w = e.w;
        float2 f0 = __half22float2(*(__half2*)&r.x);
        float2 f1 = __half22float2(*(__half2*)&r.y);
        float2 f2 = __half22float2(*(__half2*)&r.z);
        float2 f3 = __half22float2(*(__half2*)&r.w);
        a[0] += w * f0.x;  a[1] += w * f0.y;
        a[2] += w * f1.x;  a[3] += w * f1.y;
        a[4] += w * f2.x;  a[5] += w * f2.y;
        a[6] += w * f3.x;  a[7] += w * f3.y;
    }

    if (half == 0) {
#pragma unroll
        for (int q = 0; q < 8; q++) osh[lane * 8 + q] = a[q];
    }
    __syncthreads();
    if (half == 1) {
        float* op = out + (long)bs * Hh + lane * 8;
#pragma unroll
        for (int q = 0; q < 8; q++) op[q] = a[q] + osh[lane * 8 + q];
    }
}

// ---------------------------------------------------------------------------
extern "C" void kernel_launch(void* const* d_in, const int* in_sizes, int n_in,
                              void* d_out, int out_size)
{
    const int*   word_seq   = (const int*)  d_in[0];  // [B, M]
    const float* hidden     = (const float*)d_in[1];  // [B, S, H]
    const int*   labels     = (const int*)  d_in[2];  // [B, S, M]
    const float* mask       = (const float*)d_in[3];  // [B, S, M]
    const float* key_table  = (const float*)d_in[4];  // [KEY_SIZE, H]
    const float* value_tab  = (const float*)d_in[5];  // [VALUE_SIZE, H]
    float*       out        = (float*)d_out;          // [B, S, H]

    const int n8 = (VSIZE * Hh) / 8;                  // 960000
    kvmn_conv_kernel<<<(n8 + 255) / 256, 256>>>(value_tab);
    kvmn_attn_wmma<<<Bb * 16 * 2, 256>>>(word_seq, hidden, key_table);
    kvmn_gather_kernel<<<Bb * Ss, 192>>>(labels, mask, out);
}